// round 6
// baseline (speedup 1.0000x reference)
#include <cuda_runtime.h>
#include <cstdint>

#define P    1024
#define RDIM 128
#define MDIM 128

#define JS   8                       // j-splits in GEMM
#define RPB  16                      // rows per GEMM block

// Scratch (device globals — allocation-free).
__device__ __align__(16) float g_wbuf[P * P];            // softmax weights, 4 MB
__device__ __align__(16) float g_part[JS * P * MDIM];    // split-K partials, 4 MB

// =====================================================================
// Kernel A: one block per output row i.
//   scores[j] = rela[i,j,:] . att_w  (8 warps x 128 j each; 4-row
//   register double-buffer => ~48 regs => 4-5 CTAs/SM resident)
//   then in-block masked softmax -> g_wbuf[i, :]
// =====================================================================
__global__ __launch_bounds__(256, 4)
void si_row_kernel(const float* __restrict__ rela,
                   const int*   __restrict__ nei,
                   const float* __restrict__ att_w,
                   const float* __restrict__ att_b,
                   float*       __restrict__ wout)
{
    __shared__ float s_sc[P];      // raw scores for this row
    __shared__ int   s_nei[P];     // prefetched neighbor mask row
    __shared__ float s_red[16];    // cross-warp reduce scratch

    const int tid  = threadIdx.x;
    const int lane = tid & 31;
    const int warp = tid >> 5;     // 0..7
    const int i    = blockIdx.x;

    // prefetch nei row early (overlaps the big stream)
    {
        const int4 nv = reinterpret_cast<const int4*>(nei + (size_t)i * P)[tid];
        reinterpret_cast<int4*>(s_nei)[tid] = nv;
    }

    const float4 w4 = reinterpret_cast<const float4*>(att_w)[lane];

    // each warp owns j in [warp*128, warp*128+128), 32 iters x 4 rows
    const float* base = rela + ((size_t)i * P + (size_t)warp * 128) * RDIM;

    float4 cur[4], nxt[4];
    #pragma unroll
    for (int k = 0; k < 4; k++)
        cur[k] = reinterpret_cast<const float4*>(base + (size_t)k * RDIM)[lane];

    #pragma unroll 1
    for (int it = 0; it < 32; it++) {
        if (it < 31) {
            const float* nb = base + (size_t)(it + 1) * 4 * RDIM;
            #pragma unroll
            for (int k = 0; k < 4; k++)
                nxt[k] = reinterpret_cast<const float4*>(nb + (size_t)k * RDIM)[lane];
        }

        float d[4];
        #pragma unroll
        for (int k = 0; k < 4; k++)
            d[k] = fmaf(cur[k].x, w4.x,
                   fmaf(cur[k].y, w4.y,
                   fmaf(cur[k].z, w4.z, cur[k].w * w4.w)));

        // butterfly stages 16, 8 : d[k] holds partials per (lane mod 8)
        #pragma unroll
        for (int s = 16; s >= 8; s >>= 1) {
            #pragma unroll
            for (int k = 0; k < 4; k++)
                d[k] += __shfl_xor_sync(0xFFFFFFFFu, d[k], s);
        }
        // lane-group g = lane>>3 (4 groups of 8) takes row g's partials
        const int g = lane >> 3;
        float v = d[0];
        v = (g == 1) ? d[1] : v;
        v = (g == 2) ? d[2] : v;
        v = (g == 3) ? d[3] : v;
        // finish within each 8-lane group
        v += __shfl_xor_sync(0xFFFFFFFFu, v, 4);
        v += __shfl_xor_sync(0xFFFFFFFFu, v, 2);
        v += __shfl_xor_sync(0xFFFFFFFFu, v, 1);
        if ((lane & 7) == 0)
            s_sc[warp * 128 + it * 4 + g] = v;

        #pragma unroll
        for (int k = 0; k < 4; k++) cur[k] = nxt[k];
    }
    __syncthreads();

    // ---- masked softmax over the 1024 scores ----
    const float b = att_b[0];

    float vals[4];
    unsigned mbits = 0;
    float vmax = -1e30f;
    #pragma unroll
    for (int k = 0; k < 4; k++) {
        const int j = tid + k * 256;
        const bool m = (s_nei[j] > 0);
        if (m) mbits |= (1u << k);
        const float v = m ? (s_sc[j] + b) : -1e-6f;
        vals[k] = v;
        vmax = fmaxf(vmax, v);
    }
    #pragma unroll
    for (int s = 16; s; s >>= 1)
        vmax = fmaxf(vmax, __shfl_xor_sync(0xFFFFFFFFu, vmax, s));
    if (lane == 0) s_red[warp] = vmax;
    __syncthreads();
    {
        float t = s_red[lane & 7];
        #pragma unroll
        for (int s = 4; s; s >>= 1)
            t = fmaxf(t, __shfl_xor_sync(0xFFFFFFFFu, t, s));
        vmax = t;
    }

    float vsum = 0.0f;
    #pragma unroll
    for (int k = 0; k < 4; k++) {
        const float e = __expf(vals[k] - vmax);
        vals[k] = e;
        vsum += e;
    }
    #pragma unroll
    for (int s = 16; s; s >>= 1)
        vsum += __shfl_xor_sync(0xFFFFFFFFu, vsum, s);
    __syncthreads();
    if (lane == 0) s_red[8 + warp] = vsum;
    __syncthreads();
    {
        float t = s_red[8 + (lane & 7)];
        #pragma unroll
        for (int s = 4; s; s >>= 1)
            t += __shfl_xor_sync(0xFFFFFFFFu, t, s);
        vsum = t;
    }
    const float inv = 1.0f / vsum;

    float* wrow = wout + (size_t)i * P;
    #pragma unroll
    for (int k = 0; k < 4; k++) {
        const int j = tid + k * 256;
        wrow[j] = ((mbits >> k) & 1u) ? vals[k] * inv : 0.0f;
    }
}

// =====================================================================
// Kernel B1: split-K GEMM partials.
// Grid 512 = 64 i-tiles x 8 j-splits; 256 threads.
// Block (it, js): rows [it*16, it*16+16), j in [js*128, js*128+128), all m.
// Inner loop: 8 independent hidden LDGs batched per iteration (MLP=8).
// =====================================================================
__global__ __launch_bounds__(256)
void si_gemm_part_kernel(const float* __restrict__ hidden,
                         const float* __restrict__ wsrc,
                         float*       __restrict__ part)
{
    __shared__ float s_w[RPB * 128];        // weight slice, 8 KB
    __shared__ float s_part[2 * RPB * 128]; // per-sub partials, 16 KB

    const int tid = threadIdx.x;
    const int it  = blockIdx.x >> 3;        // i-tile 0..63
    const int js  = blockIdx.x & 7;         // j-split 0..7
    const int i0  = it * RPB;
    const int jb  = js * 128;

    // stage weight slice: 16 rows x 128 j = 2048 floats, 2 float4/thread
    #pragma unroll
    for (int t = 0; t < 2; t++) {
        const int o = (tid + t * 256) * 4;  // float offset in slice
        const int r = o >> 7;
        const int jj = o & 127;
        *reinterpret_cast<float4*>(&s_w[o]) =
            *reinterpret_cast<const float4*>(&wsrc[(size_t)(i0 + r) * P + jb + jj]);
    }
    __syncthreads();

    {
        const int m   = tid & 127;
        const int sub = tid >> 7;    // 0/1, 64 j each
        const int j0  = sub * 64;

        float acc[RPB];
        #pragma unroll
        for (int r = 0; r < RPB; r++) acc[r] = 0.0f;

        #pragma unroll 1
        for (int j = j0; j < j0 + 64; j += 8) {
            // batch 8 independent loads up front
            float h[8];
            #pragma unroll
            for (int t = 0; t < 8; t++)
                h[t] = hidden[(size_t)(jb + j + t) * MDIM + m];

            #pragma unroll
            for (int r = 0; r < RPB; r++) {
                const float4 w0 = *reinterpret_cast<const float4*>(&s_w[r * 128 + j]);
                const float4 w1 = *reinterpret_cast<const float4*>(&s_w[r * 128 + j + 4]);
                acc[r] = fmaf(w0.x, h[0], acc[r]);
                acc[r] = fmaf(w0.y, h[1], acc[r]);
                acc[r] = fmaf(w0.z, h[2], acc[r]);
                acc[r] = fmaf(w0.w, h[3], acc[r]);
                acc[r] = fmaf(w1.x, h[4], acc[r]);
                acc[r] = fmaf(w1.y, h[5], acc[r]);
                acc[r] = fmaf(w1.z, h[6], acc[r]);
                acc[r] = fmaf(w1.w, h[7], acc[r]);
            }
        }

        #pragma unroll
        for (int r = 0; r < RPB; r++)
            s_part[(sub * RPB + r) * 128 + m] = acc[r];
    }
    __syncthreads();

    // combine the 2 subs, write partial: part[js][i0+r][m]
    #pragma unroll
    for (int t = 0; t < 8; t++) {
        const int o = tid + t * 256;        // 0..2047
        const int r = o >> 7;
        const int mm = o & 127;
        part[(size_t)js * P * MDIM + (size_t)(i0 + r) * MDIM + mm] =
            s_part[o] + s_part[RPB * 128 + o];
    }
}

// =====================================================================
// Kernel B2: reduce 8 split-K partials -> out. 131072 floats = 32768 f4.
// =====================================================================
__global__ __launch_bounds__(256)
void si_gemm_reduce_kernel(const float* __restrict__ part,
                           float*       __restrict__ out)
{
    const int e4 = blockIdx.x * 256 + threadIdx.x;   // 0..32767
    const float4* p4 = reinterpret_cast<const float4*>(part);
    float4 s = p4[e4];
    #pragma unroll
    for (int k = 1; k < JS; k++) {
        const float4 a = p4[(size_t)k * 32768 + e4];
        s.x += a.x; s.y += a.y; s.z += a.z; s.w += a.w;
    }
    reinterpret_cast<float4*>(out)[e4] = s;
}

extern "C" void kernel_launch(void* const* d_in, const int* in_sizes, int n_in,
                              void* d_out, int out_size)
{
    (void)in_sizes; (void)n_in; (void)out_size;
    const float* hidden = (const float*)d_in[0];   // [1024,128]
    const float* rela   = (const float*)d_in[1];   // [1024,1024,128]
    // d_in[2] = corr_index : unused
    const int*   nei    = (const int*)  d_in[3];   // [1024,1024]
    const float* att_w  = (const float*)d_in[4];   // [128]
    const float* att_b  = (const float*)d_in[5];   // [1]
    float* out = (float*)d_out;                    // [1024,128] f32

    float* wbuf;  cudaGetSymbolAddress((void**)&wbuf, g_wbuf);
    float* pbuf;  cudaGetSymbolAddress((void**)&pbuf, g_part);

    si_row_kernel<<<P, 256>>>(rela, nei, att_w, att_b, wbuf);
    si_gemm_part_kernel<<<(P / RPB) * JS, 256>>>(hidden, wbuf, pbuf);
    si_gemm_reduce_kernel<<<P * MDIM / 4 / 256, 256>>>(pbuf, out);
}